// round 10
// baseline (speedup 1.0000x reference)
#include <cuda_runtime.h>
#include <cstdint>

// Embedding gather: out[token, :] = embedding[input_ids[token], :]
// input_ids: [4096] i32, embedding: [32000,1024] f32, out: [4096,1024] f32
//
// 256-bit (v8.f32) variant: sm_100+ LDG.256/STG.256 halve the warp-level
// memory instruction count vs float4 (the LSU issue + L1tex wavefront
// bookkeeping is the only busy path left; all pipes sit at ~25%).
// Geometry unchanged from the converged best: 1024 CTAs x 256 threads,
// single resident wave, 4 tokens/CTA. Each thread covers 32 B of two rows
// (tokens h and h+2, h = tid>>7) -> MLP=2, 16 data regs.

static constexpr int ROW_FLOATS     = 1024;
static constexpr int TOKENS_PER_CTA = 4;

struct alignas(32) f32x8 { float v[8]; };

__device__ __forceinline__ f32x8 ldg256(const float* p) {
    f32x8 r;
    asm volatile("ld.global.nc.v8.f32 {%0,%1,%2,%3,%4,%5,%6,%7}, [%8];"
                 : "=f"(r.v[0]), "=f"(r.v[1]), "=f"(r.v[2]), "=f"(r.v[3]),
                   "=f"(r.v[4]), "=f"(r.v[5]), "=f"(r.v[6]), "=f"(r.v[7])
                 : "l"(p));
    return r;
}
__device__ __forceinline__ void stg256(float* p, const f32x8& r) {
    asm volatile("st.global.v8.f32 [%0], {%1,%2,%3,%4,%5,%6,%7,%8};"
                 :: "l"(p),
                    "f"(r.v[0]), "f"(r.v[1]), "f"(r.v[2]), "f"(r.v[3]),
                    "f"(r.v[4]), "f"(r.v[5]), "f"(r.v[6]), "f"(r.v[7])
                 : "memory");
}

__global__ void __launch_bounds__(256)
embed_gather_v8(const int4* __restrict__ ids4,
                const float* __restrict__ emb,
                float* __restrict__ out,
                int n_tokens)
{
    const int tid  = threadIdx.x;
    const int half = tid >> 7;          // 0..1
    const int off  = (tid & 127) * 8;   // float offset within row (32 B units)
    const int base = blockIdx.x * TOKENS_PER_CTA;

    // All 4 token ids in one 16-byte broadcast load.
    int4 id4 = ids4[blockIdx.x];
    int ida = half ? id4.y : id4.x;     // token base+half
    int idb = half ? id4.w : id4.z;     // token base+half+2

    // Two independent 256-bit row loads (MLP=2).
    f32x8 va = ldg256(emb + (size_t)ida * ROW_FLOATS + off);
    f32x8 vb = ldg256(emb + (size_t)idb * ROW_FLOATS + off);

    float* dst = out + (size_t)base * ROW_FLOATS + off;
    stg256(dst + (size_t)half       * ROW_FLOATS, va);
    stg256(dst + (size_t)(half + 2) * ROW_FLOATS, vb);
}

extern "C" void kernel_launch(void* const* d_in, const int* in_sizes, int n_in,
                              void* d_out, int out_size)
{
    const int4*  ids4 = (const int4*)d_in[0];
    const float* emb  = (const float*)d_in[1];
    float*       out  = (float*)d_out;

    int n_tokens = in_sizes[0];               // 4096 (divisible by 4)
    int grid = n_tokens / TOKENS_PER_CTA;     // 1024 — single resident wave
    embed_gather_v8<<<grid, 256>>>(ids4, emb, out, n_tokens);
}